// round 3
// baseline (speedup 1.0000x reference)
#include <cuda_runtime.h>
#include <cstdint>

// Problem constants (fixed by the reference's setup_inputs)
#define CC      256
#define HH      1024
#define WW      1024
#define STRIDE  153
#define GRIDSZ  76
#define OHOFF   50
#define OWOFF   50
#define NCH     7
#define NCW     7

// Decoded 7x7 cell_erase table (scratch: __device__ global, no allocation)
__device__ unsigned char g_cell[NCH * NCW];

// cell_erase arrives with an ambiguous dtype (jax bool). Sniff the encoding:
//  - 12 leading int32 reads (48 bytes, within the 49-element buffer for any
//    candidate dtype) all in {0,1}        -> int32 encoding
//  - else all in {0.0f, 1.0f} as float   -> float32 encoding
//  - else                                -> 1-byte bool encoding
// For ~49 Bernoulli(0.5) cells the chance of misclassification is ~(2/16)^12.
__global__ void decode_cell_kernel(const void* __restrict__ cell_raw) {
    if (threadIdx.x != 0 || blockIdx.x != 0) return;
    const int32_t* ci = (const int32_t*)cell_raw;
    const float*   cf = (const float*)cell_raw;
    const unsigned char* cb = (const unsigned char*)cell_raw;

    bool is_i32 = true;
    for (int i = 0; i < 12; i++) {
        int v = ci[i];
        if (v != 0 && v != 1) { is_i32 = false; break; }
    }
    bool is_f32 = false;
    if (!is_i32) {
        is_f32 = true;
        for (int i = 0; i < 12; i++) {
            float v = cf[i];
            if (v != 0.0f && v != 1.0f) { is_f32 = false; break; }
        }
    }
    for (int i = 0; i < NCH * NCW; i++) {
        unsigned char m;
        if (is_i32)      m = (unsigned char)(ci[i] != 0);
        else if (is_f32) m = (unsigned char)(cf[i] != 0.0f);
        else             m = (unsigned char)(cb[i] != 0);
        g_cell[i] = m;
    }
}

// Elementwise masked select, float4-vectorized, with mask-predicated loads:
// skip the noise load when no lane is masked (~87% of lines) and skip the
// x load when all lanes are masked (~12% of lines).
__global__ void __launch_bounds__(256)
grid_erase_kernel(const float4* __restrict__ x,
                  const float4* __restrict__ noise,
                  float4* __restrict__ out) {
    unsigned int tid = blockIdx.x * 256u + threadIdx.x;   // 0 .. 64Mi-1
    // 4 consecutive w per thread; W/4 = 256 float4 per row
    int w0 = (int)(tid & 255u) << 2;
    int h  = (int)((tid >> 8) & 1023u);

    // Row part of the mask
    int ri = h - OHOFF;
    unsigned int m = 0;
    if (ri >= 0 && (ri % STRIDE) < GRIDSZ) {
        int cix = ri / STRIDE;               // ri<=973 -> cix<=6, clamp is a no-op
        if (cix > NCH - 1) cix = NCH - 1;
        const unsigned char* crow = g_cell + cix * NCW;
        #pragma unroll
        for (int k = 0; k < 4; k++) {
            int rj = w0 + k - OWOFF;
            if (rj >= 0 && (rj % STRIDE) < GRIDSZ) {
                int cjx = rj / STRIDE;
                if (cjx > NCW - 1) cjx = NCW - 1;
                if (crow[cjx]) m |= (1u << k);
            }
        }
    }

    float4 o;
    if (m == 0u) {
        o = x[tid];                 // common case: pure copy
    } else if (m == 0xFu) {
        o = noise[tid];             // fully-masked line: noise only
    } else {
        float4 xv = x[tid];
        float4 nv = noise[tid];
        o.x = (m & 1u) ? nv.x : xv.x;
        o.y = (m & 2u) ? nv.y : xv.y;
        o.z = (m & 4u) ? nv.z : xv.z;
        o.w = (m & 8u) ? nv.w : xv.w;
    }
    out[tid] = o;
}

extern "C" void kernel_launch(void* const* d_in, const int* in_sizes, int n_in,
                              void* d_out, int out_size) {
    const float4* x     = (const float4*)d_in[0];
    const float4* noise = (const float4*)d_in[1];
    const void*   cell  = d_in[2];
    float4*       out   = (float4*)d_out;

    decode_cell_kernel<<<1, 32>>>(cell);

    // 256*1024*1024 elements / 4 per thread = 67108864 threads
    const unsigned int n4 = (unsigned int)CC * HH * (WW / 4);
    grid_erase_kernel<<<n4 / 256, 256>>>(x, noise, out);
}

// round 6
// speedup vs baseline: 1.1086x; 1.1086x over previous
#include <cuda_runtime.h>
#include <cstdint>

// Problem constants (fixed by the reference's setup_inputs)
#define CC      256
#define HH      1024
#define WW      1024
#define STRIDE  153
#define GRIDSZ  76
#define OHOFF   50
#define OWOFF   50
#define NCH     7
#define NCW     7

#define COLS4   (WW / 4)          // 256 float4 columns per row
#define ROWS_PER_BLOCK 4

// Decoded 7x7 cell_erase table + per-(cellrow, float4-column) 4-bit lane masks.
// Scratch lives in __device__ globals (no allocation allowed).
__device__ unsigned char g_cell[NCH * NCW];
__device__ unsigned char g_colmask[NCH * COLS4];   // nibble per (cix, col)

// cell_erase arrives with an ambiguous dtype (jax bool). Sniff the encoding:
//  - 12 leading int32 reads all in {0,1}      -> int32 encoding
//  - else all in {0.0f,1.0f} as float         -> float32 encoding
//  - else                                     -> 1-byte bool encoding
// For ~49 Bernoulli(0.5) cells misclassification probability is ~(2/16)^12.
// Then build g_colmask: for each cell-row index cix and float4 column col,
// the 4-bit lane mask  OR_k( in_w(w0+k) & cell[cix][cj(w0+k)] ).
__global__ void decode_cell_kernel(const void* __restrict__ cell_raw) {
    __shared__ unsigned char s_cell[NCH * NCW];
    if (threadIdx.x == 0) {
        const int32_t* ci = (const int32_t*)cell_raw;
        const float*   cf = (const float*)cell_raw;
        const unsigned char* cb = (const unsigned char*)cell_raw;
        bool is_i32 = true;
        for (int i = 0; i < 12; i++) {
            int v = ci[i];
            if (v != 0 && v != 1) { is_i32 = false; break; }
        }
        bool is_f32 = false;
        if (!is_i32) {
            is_f32 = true;
            for (int i = 0; i < 12; i++) {
                float v = cf[i];
                if (v != 0.0f && v != 1.0f) { is_f32 = false; break; }
            }
        }
        for (int i = 0; i < NCH * NCW; i++) {
            unsigned char m;
            if (is_i32)      m = (unsigned char)(ci[i] != 0);
            else if (is_f32) m = (unsigned char)(cf[i] != 0.0f);
            else             m = (unsigned char)(cb[i] != 0);
            s_cell[i] = m;
            g_cell[i] = m;
        }
    }
    __syncthreads();

    int col = threadIdx.x;          // 0..255
    if (col < COLS4) {
        #pragma unroll
        for (int cix = 0; cix < NCH; cix++) {
            unsigned m = 0;
            #pragma unroll
            for (int k = 0; k < 4; k++) {
                int rj = col * 4 + k - OWOFF;
                if (rj >= 0 && (rj % STRIDE) < GRIDSZ) {
                    int cj = rj / STRIDE;                  // <= 6, clamp no-op
                    if (cj > NCW - 1) cj = NCW - 1;
                    if (s_cell[cix * NCW + cj]) m |= (1u << k);
                }
            }
            g_colmask[cix * COLS4 + col] = (unsigned char)m;
        }
    }
}

// Elementwise masked select. Each block owns 4 consecutive rows of one
// channel (4 | 1024, so a block never straddles a channel); each thread owns
// one float4 column in all 4 rows. All loads are issued as predicated
// LDG.128s up front (MLP ~8): x is skipped where the line is fully masked,
// noise is skipped where it is fully unmasked. Streaming cache ops avoid L2
// retention on a touch-once 3 GB stream.
__global__ void __launch_bounds__(256)
grid_erase_kernel(const float4* __restrict__ x,
                  const float4* __restrict__ noise,
                  float4* __restrict__ out) {
    const int col  = threadIdx.x;                 // 0..255
    const int row0 = blockIdx.x * ROWS_PER_BLOCK; // global row (c*1024 + h)
    const int h0   = row0 & (HH - 1);

    unsigned mrow[ROWS_PER_BLOCK];
    #pragma unroll
    for (int r = 0; r < ROWS_PER_BLOCK; r++) {
        int ri = h0 + r - OHOFF;
        unsigned m = 0;
        if (ri >= 0 && (ri % STRIDE) < GRIDSZ) {
            int cix = ri / STRIDE;                // <= 6 for ri <= 973
            m = g_colmask[cix * COLS4 + col];
        }
        mrow[r] = m;
    }

    const size_t base = (size_t)row0 * COLS4 + col;

    float4 xv[ROWS_PER_BLOCK], nv[ROWS_PER_BLOCK];
    #pragma unroll
    for (int r = 0; r < ROWS_PER_BLOCK; r++) {
        size_t i = base + (size_t)r * COLS4;
        if (mrow[r] != 0xFu) xv[r] = __ldcs(x + i);      // any lane keeps x
        if (mrow[r] != 0u)   nv[r] = __ldcs(noise + i);  // any lane erased
    }

    #pragma unroll
    for (int r = 0; r < ROWS_PER_BLOCK; r++) {
        unsigned m = mrow[r];
        float4 o;
        o.x = (m & 1u) ? nv[r].x : xv[r].x;
        o.y = (m & 2u) ? nv[r].y : xv[r].y;
        o.z = (m & 4u) ? nv[r].z : xv[r].z;
        o.w = (m & 8u) ? nv[r].w : xv[r].w;
        __stcs(out + base + (size_t)r * COLS4, o);
    }
}

extern "C" void kernel_launch(void* const* d_in, const int* in_sizes, int n_in,
                              void* d_out, int out_size) {
    const float4* x     = (const float4*)d_in[0];
    const float4* noise = (const float4*)d_in[1];
    const void*   cell  = d_in[2];
    float4*       out   = (float4*)d_out;

    decode_cell_kernel<<<1, 256>>>(cell);

    const unsigned int nrows  = (unsigned int)CC * HH;         // 262144
    const unsigned int blocks = nrows / ROWS_PER_BLOCK;        // 65536
    grid_erase_kernel<<<blocks, 256>>>(x, noise, out);
}